// round 11
// baseline (speedup 1.0000x reference)
#include <cuda_runtime.h>
#include <cuda_bf16.h>
#include <cstdint>

// Problem shapes (fixed by reference setup_inputs)
#define N_SEQ   256
#define M_GENES 2000
#define D_DIM   128

// Fused kernel with Blackwell 256-bit streaming stores.
//   Block: 256 threads = 8 warps. Warp w owns gene m = blockIdx.x*8 + w.
//   n-slab: 64 positions (blockIdx.y in 0..3).
//
//   Layout per warp: half-warp h = lane>>4 handles n = n0 + 2*i + h each
//   iteration; sublane s = lane&15 owns bytes [32s, 32s+32) of the 512B
//   output row (float4 indices 2s, 2s+1). One st.global.cs.v8.f32 per lane
//   per iteration -> 1024B per warp-store, half the store instructions and
//   L1tex wavefront entries of the STG.128 version for the same bytes.
__global__ void __launch_bounds__(256) fused_gene_embed_kernel(
    const int* __restrict__ gene_seq,      // (N, M)
    const float* __restrict__ emb,         // (M, 4, D)
    float* __restrict__ out)               // (N, M, D)
{
    const int warp = threadIdx.x >> 5;
    const int lane = threadIdx.x & 31;
    const int s    = lane & 15;             // sublane: 32B chunk within row
    const int h    = lane >> 4;             // half-warp: which of 2 n per iter
    const int m  = blockIdx.x * 8 + warp;   // grid.x = 250 (exact)
    const int n0 = blockIdx.y * 64;         // grid.y = 4   (exact)

    // ---- per-lane sequence indices covering the 64-n slab ----
    const int glA = gene_seq[(size_t)(n0 + lane)      * M_GENES + m];
    const int glB = gene_seq[(size_t)(n0 + 32 + lane) * M_GENES + m];

    // ---- load this gene's 4 rows: lane holds float4 idx 2s and 2s+1 ----
    // (each 16-lane half holds the complete 512B row; halves are duplicates)
    const float4* src = reinterpret_cast<const float4*>(emb) + (size_t)m * 128;
    float4 a0 = src[0 * 32 + 2 * s], b0 = src[0 * 32 + 2 * s + 1];
    float4 a1 = src[1 * 32 + 2 * s], b1 = src[1 * 32 + 2 * s + 1];
    float4 a2 = src[2 * 32 + 2 * s], b2 = src[2 * 32 + 2 * s + 1];
    float4 a3 = src[3 * 32 + 2 * s], b3 = src[3 * 32 + 2 * s + 1];

    // ---- normalize: reduce squared sums within each 16-lane half ----
    {
        float s0 = a0.x*a0.x + a0.y*a0.y + a0.z*a0.z + a0.w*a0.w
                 + b0.x*b0.x + b0.y*b0.y + b0.z*b0.z + b0.w*b0.w;
        float s1 = a1.x*a1.x + a1.y*a1.y + a1.z*a1.z + a1.w*a1.w
                 + b1.x*b1.x + b1.y*b1.y + b1.z*b1.z + b1.w*b1.w;
        float s2 = a2.x*a2.x + a2.y*a2.y + a2.z*a2.z + a2.w*a2.w
                 + b2.x*b2.x + b2.y*b2.y + b2.z*b2.z + b2.w*b2.w;
        float s3 = a3.x*a3.x + a3.y*a3.y + a3.z*a3.z + a3.w*a3.w
                 + b3.x*b3.x + b3.y*b3.y + b3.z*b3.z + b3.w*b3.w;
        #pragma unroll
        for (int off = 8; off > 0; off >>= 1) {     // xor within 16-lane half
            s0 += __shfl_xor_sync(0xFFFFFFFFu, s0, off);
            s1 += __shfl_xor_sync(0xFFFFFFFFu, s1, off);
            s2 += __shfl_xor_sync(0xFFFFFFFFu, s2, off);
            s3 += __shfl_xor_sync(0xFFFFFFFFu, s3, off);
        }
        // Norms ~0.12 >> 1e-12 eps clamp; rsqrtf is exact enough (tol 1e-3).
        const float i0 = rsqrtf(s0);
        const float i1 = rsqrtf(s1);
        const float i2 = rsqrtf(s2);
        const float i3 = rsqrtf(s3);
        a0.x*=i0; a0.y*=i0; a0.z*=i0; a0.w*=i0; b0.x*=i0; b0.y*=i0; b0.z*=i0; b0.w*=i0;
        a1.x*=i1; a1.y*=i1; a1.z*=i1; a1.w*=i1; b1.x*=i1; b1.y*=i1; b1.z*=i1; b1.w*=i1;
        a2.x*=i2; a2.y*=i2; a2.z*=i2; a2.w*=i2; b2.x*=i2; b2.y*=i2; b2.z*=i2; b2.w*=i2;
        a3.x*=i3; a3.y*=i3; a3.z*=i3; a3.w*=i3; b3.x*=i3; b3.y*=i3; b3.z*=i3; b3.w*=i3;
    }

    // ---- 256-bit streaming-store loop: 2 n-rows per iteration ----
    // Lane writes 32B at out[(n0+2i+h)*M + m][32s..32s+32).
    float* ob = out + ((size_t)(n0 + h) * M_GENES + m) * D_DIM + 8 * s;
    const size_t step2 = (size_t)M_GENES * D_DIM * 2;   // advance 2 n per iter

    #pragma unroll 8
    for (int i = 0; i < 32; i++) {
        // local n for this lane = 2*i + h; its index lives in glA (n<32) or glB
        const int g = __shfl_sync(0xFFFFFFFFu, (2 * i + 1 < 32) ? glA : glB,
                                  (2 * i + h) & 31);
        const float4 va = (g == 0) ? a0 : (g == 1) ? a1 : (g == 2) ? a2 : a3;
        const float4 vb = (g == 0) ? b0 : (g == 1) ? b1 : (g == 2) ? b2 : b3;
        asm volatile(
            "st.global.cs.v8.f32 [%0], {%1, %2, %3, %4, %5, %6, %7, %8};"
            :: "l"(ob),
               "f"(va.x), "f"(va.y), "f"(va.z), "f"(va.w),
               "f"(vb.x), "f"(vb.y), "f"(vb.z), "f"(vb.w)
            : "memory");
        ob += step2;
    }
}

extern "C" void kernel_launch(void* const* d_in, const int* in_sizes, int n_in,
                              void* d_out, int out_size) {
    const int* gene_seq = (const int*)d_in[0];      // (256, 2000) int32
    const float* emb    = (const float*)d_in[1];    // (2000, 4, 128) fp32
    float* out          = (float*)d_out;            // (256, 2000, 128) fp32

    dim3 grid(M_GENES / 8, N_SEQ / 64, 1);          // (250, 4)
    fused_gene_embed_kernel<<<grid, 256>>>(gene_seq, emb, out);
}

// round 12
// speedup vs baseline: 1.0935x; 1.0935x over previous
#include <cuda_runtime.h>
#include <cuda_bf16.h>
#include <cstdint>

// Problem shapes (fixed by reference setup_inputs)
#define N_SEQ   256
#define M_GENES 2000
#define D_DIM   128

// FINAL kernel — R3 structure, twice-reproduced best (43.1 / 43.4 us).
//
//   Block: 256 threads = 8 warps. Warp w owns gene m = blockIdx.x*8 + w.
//   Tile:  32 sequence positions (blockIdx.y), matching warp size.
//
//   Prologue (per warp, registers only):
//     - 4x LDG.128: the gene's 4 embedding rows (L2-resident, 2 KB)
//     - butterfly-reduce the 4 squared norms (result in every lane)
//     - scale rows in registers -> r0..r3 (16 regs)
//     - lane nn loads gene_seq[n0+nn][m] (one 4B LDG per lane)
//
//   Inner loop (32 iterations): shfl index broadcast, 4-way register
//   select, one streaming STG.128 (.cs). Self-paced store issue matches
//   the HBM write drain rate — measured best for bench steady state.
//
//   262 MB mandated fp32 output / ~6.1 TB/s sustained write BW = ~43 us
//   floor. Five attempts to pierce it (TMA bulk stores, L2 write-back
//   retention, partitioned pinning, wave reshape, 256-bit v8 stores) all
//   regressed or were neutral; this kernel runs at ~99% of the ceiling.
__global__ void __launch_bounds__(256) fused_gene_embed_kernel(
    const int* __restrict__ gene_seq,      // (N, M)
    const float* __restrict__ emb,         // (M, 4, D)
    float* __restrict__ out)               // (N, M, D)
{
    const int warp = threadIdx.x >> 5;
    const int lane = threadIdx.x & 31;
    const int m  = blockIdx.x * 8 + warp;   // grid.x = 250 (exact)
    const int n0 = blockIdx.y * 32;         // grid.y = 8   (exact)

    // ---- load this gene's 4 table rows into registers ----
    const float4* src = reinterpret_cast<const float4*>(emb) + (size_t)m * 4 * 32;
    float4 r0 = src[lane];
    float4 r1 = src[32 + lane];
    float4 r2 = src[64 + lane];
    float4 r3 = src[96 + lane];

    // ---- per-lane sequence index (lane == nn within the 32-tile) ----
    const int gl = gene_seq[(size_t)(n0 + lane) * M_GENES + m];

    // ---- normalize rows in registers (butterfly keeps norm in all lanes) ----
    {
        float s0 = r0.x*r0.x + r0.y*r0.y + r0.z*r0.z + r0.w*r0.w;
        float s1 = r1.x*r1.x + r1.y*r1.y + r1.z*r1.z + r1.w*r1.w;
        float s2 = r2.x*r2.x + r2.y*r2.y + r2.z*r2.z + r2.w*r2.w;
        float s3 = r3.x*r3.x + r3.y*r3.y + r3.z*r3.z + r3.w*r3.w;
        #pragma unroll
        for (int off = 16; off > 0; off >>= 1) {
            s0 += __shfl_xor_sync(0xFFFFFFFFu, s0, off);
            s1 += __shfl_xor_sync(0xFFFFFFFFu, s1, off);
            s2 += __shfl_xor_sync(0xFFFFFFFFu, s2, off);
            s3 += __shfl_xor_sync(0xFFFFFFFFu, s3, off);
        }
        const float i0 = 1.0f / fmaxf(sqrtf(s0), 1e-12f);
        const float i1 = 1.0f / fmaxf(sqrtf(s1), 1e-12f);
        const float i2 = 1.0f / fmaxf(sqrtf(s2), 1e-12f);
        const float i3 = 1.0f / fmaxf(sqrtf(s3), 1e-12f);
        r0.x *= i0; r0.y *= i0; r0.z *= i0; r0.w *= i0;
        r1.x *= i1; r1.y *= i1; r1.z *= i1; r1.w *= i1;
        r2.x *= i2; r2.y *= i2; r2.z *= i2; r2.w *= i2;
        r3.x *= i3; r3.y *= i3; r3.z *= i3; r3.w *= i3;
    }

    // ---- pure streaming-store loop ----
    float4* ob = reinterpret_cast<float4*>(out)
               + ((size_t)n0 * M_GENES + m) * 32 + lane;
    const size_t row_stride = (size_t)M_GENES * 32;   // one n step

    #pragma unroll 8
    for (int nn = 0; nn < 32; nn++) {
        const int g = __shfl_sync(0xFFFFFFFFu, gl, nn);
        const float4 v = (g == 0) ? r0 : (g == 1) ? r1 : (g == 2) ? r2 : r3;
        __stcs(ob, v);
        ob += row_stride;
    }
}

extern "C" void kernel_launch(void* const* d_in, const int* in_sizes, int n_in,
                              void* d_out, int out_size) {
    const int* gene_seq = (const int*)d_in[0];      // (256, 2000) int32
    const float* emb    = (const float*)d_in[1];    // (2000, 4, 128) fp32
    float* out          = (float*)d_out;            // (256, 2000, 128) fp32

    dim3 grid(M_GENES / 8, N_SEQ / 32, 1);          // (250, 8)
    fused_gene_embed_kernel<<<grid, 256>>>(gene_seq, emb, out);
}

// round 13
// speedup vs baseline: 1.1016x; 1.0074x over previous
#include <cuda_runtime.h>
#include <cuda_bf16.h>
#include <cstdint>

// Problem shapes (fixed by reference setup_inputs)
#define N_SEQ   256
#define M_GENES 2000
#define D_DIM   128

// FINAL kernel — converged at the HBM write wall (43.1-43.5 us over three
// reproductions; ~99% of the ~6.1 TB/s sustained pure-write ceiling for the
// mandated 262 MB fp32 output).
//
//   Block: 256 threads = 8 warps. Warp w owns gene m = blockIdx.x*8 + w.
//   Tile:  32 sequence positions (blockIdx.y), matching warp size.
//
//   Prologue (per warp, registers only):
//     - 4x LDG.128: the gene's 4 embedding rows (L2-resident, 2 KB)
//     - butterfly-reduce the 4 squared norms (result in every lane)
//     - scale rows in registers -> r0..r3 (16 regs)
//     - lane nn loads gene_seq[n0+nn][m] (one 4B LDG per lane)
//
//   Inner loop (32 iterations): shfl index broadcast, 4-way register
//   select, one streaming STG.128 (.cs evict-first). Self-paced store
//   issue matches the HBM drain rate — measured best for bench steady
//   state. Tested-and-rejected alternatives: SMEM-staged rows, TMA bulk
//   4KB stores, L2 write-back retention, partitioned L2 pinning, grid
//   reshapes, 256-bit v8 stores (all neutral or regressions).
__global__ void __launch_bounds__(256) fused_gene_embed_kernel(
    const int* __restrict__ gene_seq,      // (N, M)
    const float* __restrict__ emb,         // (M, 4, D)
    float* __restrict__ out)               // (N, M, D)
{
    const int warp = threadIdx.x >> 5;
    const int lane = threadIdx.x & 31;
    const int m  = blockIdx.x * 8 + warp;   // grid.x = 250 (exact)
    const int n0 = blockIdx.y * 32;         // grid.y = 8   (exact)

    // ---- load this gene's 4 table rows into registers ----
    const float4* src = reinterpret_cast<const float4*>(emb) + (size_t)m * 4 * 32;
    float4 r0 = src[lane];
    float4 r1 = src[32 + lane];
    float4 r2 = src[64 + lane];
    float4 r3 = src[96 + lane];

    // ---- per-lane sequence index (lane == nn within the 32-tile) ----
    const int gl = gene_seq[(size_t)(n0 + lane) * M_GENES + m];

    // ---- normalize rows in registers (butterfly keeps norm in all lanes) ----
    {
        float s0 = r0.x*r0.x + r0.y*r0.y + r0.z*r0.z + r0.w*r0.w;
        float s1 = r1.x*r1.x + r1.y*r1.y + r1.z*r1.z + r1.w*r1.w;
        float s2 = r2.x*r2.x + r2.y*r2.y + r2.z*r2.z + r2.w*r2.w;
        float s3 = r3.x*r3.x + r3.y*r3.y + r3.z*r3.z + r3.w*r3.w;
        #pragma unroll
        for (int off = 16; off > 0; off >>= 1) {
            s0 += __shfl_xor_sync(0xFFFFFFFFu, s0, off);
            s1 += __shfl_xor_sync(0xFFFFFFFFu, s1, off);
            s2 += __shfl_xor_sync(0xFFFFFFFFu, s2, off);
            s3 += __shfl_xor_sync(0xFFFFFFFFu, s3, off);
        }
        const float i0 = 1.0f / fmaxf(sqrtf(s0), 1e-12f);
        const float i1 = 1.0f / fmaxf(sqrtf(s1), 1e-12f);
        const float i2 = 1.0f / fmaxf(sqrtf(s2), 1e-12f);
        const float i3 = 1.0f / fmaxf(sqrtf(s3), 1e-12f);
        r0.x *= i0; r0.y *= i0; r0.z *= i0; r0.w *= i0;
        r1.x *= i1; r1.y *= i1; r1.z *= i1; r1.w *= i1;
        r2.x *= i2; r2.y *= i2; r2.z *= i2; r2.w *= i2;
        r3.x *= i3; r3.y *= i3; r3.z *= i3; r3.w *= i3;
    }

    // ---- pure streaming-store loop ----
    float4* ob = reinterpret_cast<float4*>(out)
               + ((size_t)n0 * M_GENES + m) * 32 + lane;
    const size_t row_stride = (size_t)M_GENES * 32;   // one n step

    #pragma unroll 8
    for (int nn = 0; nn < 32; nn++) {
        const int g = __shfl_sync(0xFFFFFFFFu, gl, nn);
        const float4 v = (g == 0) ? r0 : (g == 1) ? r1 : (g == 2) ? r2 : r3;
        __stcs(ob, v);
        ob += row_stride;
    }
}

extern "C" void kernel_launch(void* const* d_in, const int* in_sizes, int n_in,
                              void* d_out, int out_size) {
    const int* gene_seq = (const int*)d_in[0];      // (256, 2000) int32
    const float* emb    = (const float*)d_in[1];    // (2000, 4, 128) fp32
    float* out          = (float*)d_out;            // (256, 2000, 128) fp32

    dim3 grid(M_GENES / 8, N_SEQ / 32, 1);          // (250, 8)
    fused_gene_embed_kernel<<<grid, 256>>>(gene_seq, emb, out);
}

// round 14
// speedup vs baseline: 1.1024x; 1.0007x over previous
#include <cuda_runtime.h>
#include <cuda_bf16.h>
#include <cstdint>

// Problem shapes (fixed by reference setup_inputs)
#define N_SEQ   256
#define M_GENES 2000
#define D_DIM   128

// R3-family kernel, launch-order experiment: grid swapped to (8, 250) so
// each scheduling wave of ~148 CTAs spans all 8 n-slabs (concurrent write
// footprint spread across the full 262 MB instead of one 32 MB slab).
// Kernel body byte-identical to the converged best (43.10-43.49 us band).
__global__ void __launch_bounds__(256) fused_gene_embed_kernel(
    const int* __restrict__ gene_seq,      // (N, M)
    const float* __restrict__ emb,         // (M, 4, D)
    float* __restrict__ out)               // (N, M, D)
{
    const int warp = threadIdx.x >> 5;
    const int lane = threadIdx.x & 31;
    const int m  = blockIdx.y * 8 + warp;   // grid.y = 250 (exact)
    const int n0 = blockIdx.x * 32;         // grid.x = 8   (exact)

    // ---- load this gene's 4 table rows into registers ----
    const float4* src = reinterpret_cast<const float4*>(emb) + (size_t)m * 4 * 32;
    float4 r0 = src[lane];
    float4 r1 = src[32 + lane];
    float4 r2 = src[64 + lane];
    float4 r3 = src[96 + lane];

    // ---- per-lane sequence index (lane == nn within the 32-tile) ----
    const int gl = gene_seq[(size_t)(n0 + lane) * M_GENES + m];

    // ---- normalize rows in registers (butterfly keeps norm in all lanes) ----
    {
        float s0 = r0.x*r0.x + r0.y*r0.y + r0.z*r0.z + r0.w*r0.w;
        float s1 = r1.x*r1.x + r1.y*r1.y + r1.z*r1.z + r1.w*r1.w;
        float s2 = r2.x*r2.x + r2.y*r2.y + r2.z*r2.z + r2.w*r2.w;
        float s3 = r3.x*r3.x + r3.y*r3.y + r3.z*r3.z + r3.w*r3.w;
        #pragma unroll
        for (int off = 16; off > 0; off >>= 1) {
            s0 += __shfl_xor_sync(0xFFFFFFFFu, s0, off);
            s1 += __shfl_xor_sync(0xFFFFFFFFu, s1, off);
            s2 += __shfl_xor_sync(0xFFFFFFFFu, s2, off);
            s3 += __shfl_xor_sync(0xFFFFFFFFu, s3, off);
        }
        const float i0 = 1.0f / fmaxf(sqrtf(s0), 1e-12f);
        const float i1 = 1.0f / fmaxf(sqrtf(s1), 1e-12f);
        const float i2 = 1.0f / fmaxf(sqrtf(s2), 1e-12f);
        const float i3 = 1.0f / fmaxf(sqrtf(s3), 1e-12f);
        r0.x *= i0; r0.y *= i0; r0.z *= i0; r0.w *= i0;
        r1.x *= i1; r1.y *= i1; r1.z *= i1; r1.w *= i1;
        r2.x *= i2; r2.y *= i2; r2.z *= i2; r2.w *= i2;
        r3.x *= i3; r3.y *= i3; r3.z *= i3; r3.w *= i3;
    }

    // ---- pure streaming-store loop ----
    float4* ob = reinterpret_cast<float4*>(out)
               + ((size_t)n0 * M_GENES + m) * 32 + lane;
    const size_t row_stride = (size_t)M_GENES * 32;   // one n step

    #pragma unroll 8
    for (int nn = 0; nn < 32; nn++) {
        const int g = __shfl_sync(0xFFFFFFFFu, gl, nn);
        const float4 v = (g == 0) ? r0 : (g == 1) ? r1 : (g == 2) ? r2 : r3;
        __stcs(ob, v);
        ob += row_stride;
    }
}

extern "C" void kernel_launch(void* const* d_in, const int* in_sizes, int n_in,
                              void* d_out, int out_size) {
    const int* gene_seq = (const int*)d_in[0];      // (256, 2000) int32
    const float* emb    = (const float*)d_in[1];    // (2000, 4, 128) fp32
    float* out          = (float*)d_out;            // (256, 2000, 128) fp32

    dim3 grid(N_SEQ / 32, M_GENES / 8, 1);          // (8, 250) — swapped order
    fused_gene_embed_kernel<<<grid, 256>>>(gene_seq, emb, out);
}

// round 15
// speedup vs baseline: 1.1032x; 1.0007x over previous
#include <cuda_runtime.h>
#include <cuda_bf16.h>
#include <cstdint>

// Problem shapes (fixed by reference setup_inputs)
#define N_SEQ   256
#define M_GENES 2000
#define D_DIM   128

// FINAL kernel — converged at the HBM write wall.
// Best measured: 43.10 us; 5 reproductions within 43.10-43.49 us.
// 262 MB mandated fp32 output / ~6.1 TB/s sustained pure-write BW = ~43 us
// physical floor; this kernel runs at ~99% of that measured ceiling.
//
//   Block: 256 threads = 8 warps. Warp w owns gene m = blockIdx.x*8 + w.
//   Tile:  32 sequence positions (blockIdx.y), matching warp size.
//
//   Prologue (per warp, registers only):
//     - 4x LDG.128: the gene's 4 embedding rows (L2-resident, 2 KB)
//     - butterfly-reduce the 4 squared norms (result in every lane)
//     - scale rows in registers -> r0..r3 (16 regs)
//     - lane nn loads gene_seq[n0+nn][m] (one 4B LDG per lane)
//
//   Inner loop (32 iterations): shfl index broadcast, 4-way register
//   select, one streaming STG.128 (.cs evict-first). Self-paced store
//   issue matches the HBM drain rate — measured best for replay steady
//   state. Tested-and-rejected alternatives: SMEM-staged rows, TMA bulk
//   4KB stores, L2 write-back retention, partitioned L2 pinning, grid
//   reshapes, 256-bit v8 stores, launch-order footprint spread.
__global__ void __launch_bounds__(256) fused_gene_embed_kernel(
    const int* __restrict__ gene_seq,      // (N, M)
    const float* __restrict__ emb,         // (M, 4, D)
    float* __restrict__ out)               // (N, M, D)
{
    const int warp = threadIdx.x >> 5;
    const int lane = threadIdx.x & 31;
    const int m  = blockIdx.x * 8 + warp;   // grid.x = 250 (exact)
    const int n0 = blockIdx.y * 32;         // grid.y = 8   (exact)

    // ---- load this gene's 4 table rows into registers ----
    const float4* src = reinterpret_cast<const float4*>(emb) + (size_t)m * 4 * 32;
    float4 r0 = src[lane];
    float4 r1 = src[32 + lane];
    float4 r2 = src[64 + lane];
    float4 r3 = src[96 + lane];

    // ---- per-lane sequence index (lane == nn within the 32-tile) ----
    const int gl = gene_seq[(size_t)(n0 + lane) * M_GENES + m];

    // ---- normalize rows in registers (butterfly keeps norm in all lanes) ----
    {
        float s0 = r0.x*r0.x + r0.y*r0.y + r0.z*r0.z + r0.w*r0.w;
        float s1 = r1.x*r1.x + r1.y*r1.y + r1.z*r1.z + r1.w*r1.w;
        float s2 = r2.x*r2.x + r2.y*r2.y + r2.z*r2.z + r2.w*r2.w;
        float s3 = r3.x*r3.x + r3.y*r3.y + r3.z*r3.z + r3.w*r3.w;
        #pragma unroll
        for (int off = 16; off > 0; off >>= 1) {
            s0 += __shfl_xor_sync(0xFFFFFFFFu, s0, off);
            s1 += __shfl_xor_sync(0xFFFFFFFFu, s1, off);
            s2 += __shfl_xor_sync(0xFFFFFFFFu, s2, off);
            s3 += __shfl_xor_sync(0xFFFFFFFFu, s3, off);
        }
        const float i0 = 1.0f / fmaxf(sqrtf(s0), 1e-12f);
        const float i1 = 1.0f / fmaxf(sqrtf(s1), 1e-12f);
        const float i2 = 1.0f / fmaxf(sqrtf(s2), 1e-12f);
        const float i3 = 1.0f / fmaxf(sqrtf(s3), 1e-12f);
        r0.x *= i0; r0.y *= i0; r0.z *= i0; r0.w *= i0;
        r1.x *= i1; r1.y *= i1; r1.z *= i1; r1.w *= i1;
        r2.x *= i2; r2.y *= i2; r2.z *= i2; r2.w *= i2;
        r3.x *= i3; r3.y *= i3; r3.z *= i3; r3.w *= i3;
    }

    // ---- pure streaming-store loop ----
    float4* ob = reinterpret_cast<float4*>(out)
               + ((size_t)n0 * M_GENES + m) * 32 + lane;
    const size_t row_stride = (size_t)M_GENES * 32;   // one n step

    #pragma unroll 8
    for (int nn = 0; nn < 32; nn++) {
        const int g = __shfl_sync(0xFFFFFFFFu, gl, nn);
        const float4 v = (g == 0) ? r0 : (g == 1) ? r1 : (g == 2) ? r2 : r3;
        __stcs(ob, v);
        ob += row_stride;
    }
}

extern "C" void kernel_launch(void* const* d_in, const int* in_sizes, int n_in,
                              void* d_out, int out_size) {
    const int* gene_seq = (const int*)d_in[0];      // (256, 2000) int32
    const float* emb    = (const float*)d_in[1];    // (2000, 4, 128) fp32
    float* out          = (float*)d_out;            // (256, 2000, 128) fp32

    dim3 grid(M_GENES / 8, N_SEQ / 32, 1);          // (250, 8)
    fused_gene_embed_kernel<<<grid, 256>>>(gene_seq, emb, out);
}